// round 1
// baseline (speedup 1.0000x reference)
#include <cuda_runtime.h>
#include <math.h>

#define VOCABSZ 32000
#define WORDVEC 256
#define HIDDEN  512
#define TSTEPS  256
#define NBATCH  16
#define G4      2048   // 4*HIDDEN

// ---------------- scratch (static device globals; no allocation) ----------------
__device__ float    g_xw[TSTEPS * NBATCH * G4];       // [t][n][4H]  33.5 MB
__device__ float    g_hall[TSTEPS * NBATCH * HIDDEN]; // [t][n][H]    8.4 MB
__device__ float    g_h[NBATCH * HIDDEN];
__device__ float    g_c[NBATCH * HIDDEN];
__device__ float    g_part[4 * NBATCH * G4];          // k-chunk partials
__device__ unsigned g_barc[1024];                     // barrier counters
__device__ float    g_nll[TSTEPS * NBATCH];

// ---------------- helpers ----------------
__device__ __forceinline__ float sigf(float x) {
    return __fdividef(1.f, 1.f + __expf(-x));
}
__device__ __forceinline__ float tanhf_fast(float x) {
    return __fdividef(2.f, 1.f + __expf(-2.f * x)) - 1.f;
}

// software grid barrier: each barrier index used exactly once per launch
__device__ __forceinline__ void grid_barrier(int idx, unsigned nblocks) {
    __threadfence();
    __syncthreads();
    if (threadIdx.x == 0) {
        atomicAdd(&g_barc[idx], 1u);
        volatile unsigned* p = &g_barc[idx];
        while (*p < nblocks) { }
        __threadfence();
    }
    __syncthreads();
}

// ---------------- init: reset mutable state every launch ----------------
__global__ void init_kernel(const float* __restrict__ h_init) {
    int i = blockIdx.x * blockDim.x + threadIdx.x;
    if (i < 1024) g_barc[i] = 0u;
    if (i < NBATCH * HIDDEN) {
        g_h[i] = h_init[i & (HIDDEN - 1)];
        g_c[i] = 0.f;
    }
}

// ---------------- embed gather + xw = x@Wx + b ----------------
// grid: 256 t * 8 k-tiles; block 256 threads. Each thread: one k column, 16 batch rows.
__global__ void __launch_bounds__(256) embed_xw_kernel(
    const int* __restrict__ captions, const float* __restrict__ W_embed,
    const float* __restrict__ Wx, const float* __restrict__ b)
{
    const int t   = blockIdx.x >> 3;
    const int kt  = blockIdx.x & 7;
    const int tid = threadIdx.x;

    __shared__ __align__(16) float x_sh[WORDVEC * 20]; // [d][n] stride 20 (pad)
    __shared__ int tok[NBATCH];
    if (tid < NBATCH) tok[tid] = captions[tid * 257 + t];  // cap_in[n][t]
    __syncthreads();

    #pragma unroll
    for (int i = 0; i < 16; ++i) {           // n = i, d = tid
        x_sh[tid * 20 + i] = W_embed[tok[i] * WORDVEC + tid];
    }
    __syncthreads();

    const int k = kt * 256 + tid;
    float acc[16];
    const float bk = b[k];
    #pragma unroll
    for (int n = 0; n < 16; ++n) acc[n] = bk;

    #pragma unroll 4
    for (int d = 0; d < WORDVEC; ++d) {
        float w = Wx[d * G4 + k];
        float4 h0 = *(const float4*)&x_sh[d * 20 + 0];
        float4 h1 = *(const float4*)&x_sh[d * 20 + 4];
        float4 h2 = *(const float4*)&x_sh[d * 20 + 8];
        float4 h3 = *(const float4*)&x_sh[d * 20 + 12];
        acc[0]  = fmaf(h0.x, w, acc[0]);  acc[1]  = fmaf(h0.y, w, acc[1]);
        acc[2]  = fmaf(h0.z, w, acc[2]);  acc[3]  = fmaf(h0.w, w, acc[3]);
        acc[4]  = fmaf(h1.x, w, acc[4]);  acc[5]  = fmaf(h1.y, w, acc[5]);
        acc[6]  = fmaf(h1.z, w, acc[6]);  acc[7]  = fmaf(h1.w, w, acc[7]);
        acc[8]  = fmaf(h2.x, w, acc[8]);  acc[9]  = fmaf(h2.y, w, acc[9]);
        acc[10] = fmaf(h2.z, w, acc[10]); acc[11] = fmaf(h2.w, w, acc[11]);
        acc[12] = fmaf(h3.x, w, acc[12]); acc[13] = fmaf(h3.y, w, acc[13]);
        acc[14] = fmaf(h3.z, w, acc[14]); acc[15] = fmaf(h3.w, w, acc[15]);
    }
    float* o = &g_xw[(t * NBATCH) * G4 + k];
    #pragma unroll
    for (int n = 0; n < 16; ++n) o[n * G4] = acc[n];
}

// ---------------- persistent LSTM scan ----------------
// 128 blocks x 256 threads; block = (jt 0..31 [64 j-cols], kc 0..3 [128 k]).
// Phase1: partial a = h @ Wh over k-chunk -> g_part. barrier.
// Phase2: first 8192 threads: gates + c/h update. barrier.
__global__ void __launch_bounds__(256) lstm_kernel(const float* __restrict__ Wh) {
    const int bid = blockIdx.x, tid = threadIdx.x;
    const int jt = bid & 31, kc = bid >> 5;
    const int jq = tid & 15, nn = tid >> 4;
    const int jcol = jt * 16 + jq;               // float4 column 0..511
    __shared__ __align__(16) float h_sh[NBATCH * 128];
    const float4* __restrict__ Wh4 = (const float4*)Wh;

    int bi = 0;
    for (int t = 0; t < TSTEPS; ++t) {
        // load this block's k-slice of h (written by other blocks last step -> .cg)
        #pragma unroll
        for (int i = 0; i < 8; ++i) {
            int idx = tid + i * 256;             // n*128 + k
            int n = idx >> 7, k = idx & 127;
            h_sh[idx] = __ldcg(&g_h[n * HIDDEN + kc * 128 + k]);
        }
        __syncthreads();

        float4 a = make_float4(0.f, 0.f, 0.f, 0.f);
        const float* hp = &h_sh[nn * 128];
        #pragma unroll 4
        for (int k = 0; k < 128; ++k) {
            float hv = hp[k];
            float4 w = Wh4[(kc * 128 + k) * 512 + jcol];
            a.x = fmaf(hv, w.x, a.x);
            a.y = fmaf(hv, w.y, a.y);
            a.z = fmaf(hv, w.z, a.z);
            a.w = fmaf(hv, w.w, a.w);
        }
        float* gp = &g_part[(kc * NBATCH + nn) * G4 + jcol * 4];
        gp[0] = a.x; gp[1] = a.y; gp[2] = a.z; gp[3] = a.w;

        grid_barrier(bi++, 128);

        int gidx = bid * 256 + tid;
        if (gidx < NBATCH * HIDDEN) {
            int n = gidx >> 9, h = gidx & 511;
            float av[4];
            #pragma unroll
            for (int g = 0; g < 4; ++g) {
                int col = g * HIDDEN + h;
                float s = g_xw[(t * NBATCH + n) * G4 + col];
                #pragma unroll
                for (int q = 0; q < 4; ++q)
                    s += __ldcg(&g_part[(q * NBATCH + n) * G4 + col]);
                av[g] = s;
            }
            float ig = sigf(av[0]);
            float fg = sigf(av[1]);
            float og = sigf(av[2]);
            float gg = tanhf_fast(av[3]);
            float c  = fg * g_c[gidx] + ig * gg;
            float hh = og * tanhf_fast(c);
            g_c[gidx] = c;
            g_h[gidx] = hh;
            g_hall[t * (NBATCH * HIDDEN) + gidx] = hh;
        }
        grid_barrier(bi++, 128);
    }
}

// ---------------- vocab projection + streaming log-softmax NLL ----------------
// 256 blocks (one per t) x 256 threads; 16-row register blocking; online LSE.
__global__ void __launch_bounds__(256) vocab_kernel(
    const float* __restrict__ Wv, const float* __restrict__ bv,
    const int* __restrict__ captions)
{
    const int t = blockIdx.x, tid = threadIdx.x;
    __shared__ __align__(16) float h_sh[HIDDEN * 20];  // [k][n] stride 20
    __shared__ float red_m[8][16], red_s[8][16];
    __shared__ float sh_lt[16];
    __shared__ int   sh_tg[16];

    if (tid < 16) sh_tg[tid] = captions[tid * 257 + t + 1];  // cap_out[n][t]
    #pragma unroll
    for (int i = 0; i < 32; ++i) {
        int idx = tid + i * 256;                 // n*512 + k
        int n = idx >> 9, k = idx & 511;
        h_sh[k * 20 + n] = g_hall[t * (NBATCH * HIDDEN) + idx];
    }
    __syncthreads();

    float m[16], s[16];
    int tg[16];
    #pragma unroll
    for (int n = 0; n < 16; ++n) { m[n] = -3.0e38f; s[n] = 0.f; tg[n] = sh_tg[n]; }

    for (int vi = 0; vi < VOCABSZ / 256; ++vi) {
        int v = tid + vi * 256;
        float acc[16];
        float bvv = bv[v];
        #pragma unroll
        for (int n = 0; n < 16; ++n) acc[n] = bvv;

        #pragma unroll 4
        for (int k = 0; k < HIDDEN; ++k) {
            float w = Wv[k * VOCABSZ + v];
            float4 h0 = *(const float4*)&h_sh[k * 20 + 0];
            float4 h1 = *(const float4*)&h_sh[k * 20 + 4];
            float4 h2 = *(const float4*)&h_sh[k * 20 + 8];
            float4 h3 = *(const float4*)&h_sh[k * 20 + 12];
            acc[0]  = fmaf(h0.x, w, acc[0]);  acc[1]  = fmaf(h0.y, w, acc[1]);
            acc[2]  = fmaf(h0.z, w, acc[2]);  acc[3]  = fmaf(h0.w, w, acc[3]);
            acc[4]  = fmaf(h1.x, w, acc[4]);  acc[5]  = fmaf(h1.y, w, acc[5]);
            acc[6]  = fmaf(h1.z, w, acc[6]);  acc[7]  = fmaf(h1.w, w, acc[7]);
            acc[8]  = fmaf(h2.x, w, acc[8]);  acc[9]  = fmaf(h2.y, w, acc[9]);
            acc[10] = fmaf(h2.z, w, acc[10]); acc[11] = fmaf(h2.w, w, acc[11]);
            acc[12] = fmaf(h3.x, w, acc[12]); acc[13] = fmaf(h3.w == h3.w ? h3.w : 0.f, 0.f, acc[13]); // placeholder fixed below
            acc[13] = fmaf(h3.y, w, acc[13]);
            acc[14] = fmaf(h3.z, w, acc[14]); acc[15] = fmaf(h3.w, w, acc[15]);
        }
        #pragma unroll
        for (int n = 0; n < 16; ++n) {
            float l = acc[n];
            if (v == tg[n]) sh_lt[n] = l;
            float nm = fmaxf(m[n], l);
            s[n] = s[n] * __expf(m[n] - nm) + __expf(l - nm);
            m[n] = nm;
        }
    }

    // warp-level (m,s) reduction per row
    #pragma unroll
    for (int off = 16; off > 0; off >>= 1) {
        #pragma unroll
        for (int n = 0; n < 16; ++n) {
            float mo = __shfl_down_sync(0xffffffffu, m[n], off);
            float so = __shfl_down_sync(0xffffffffu, s[n], off);
            float nm = fmaxf(m[n], mo);
            s[n] = s[n] * __expf(m[n] - nm) + so * __expf(mo - nm);
            m[n] = nm;
        }
    }
    int wid = tid >> 5, lane = tid & 31;
    if (lane == 0) {
        #pragma unroll
        for (int n = 0; n < 16; ++n) { red_m[wid][n] = m[n]; red_s[wid][n] = s[n]; }
    }
    __syncthreads();

    if (tid < 16) {
        int n = tid;
        float M = red_m[0][n], S = red_s[0][n];
        #pragma unroll
        for (int w = 1; w < 8; ++w) {
            float mo = red_m[w][n], so = red_s[w][n];
            float nm = fmaxf(M, mo);
            S = S * __expf(M - nm) + so * __expf(mo - nm);
            M = nm;
        }
        float lse = M + logf(S);
        float nll = (sh_tg[n] != 0) ? (lse - sh_lt[n]) : 0.f;
        g_nll[t * 16 + n] = nll;
    }
}

// ---------------- deterministic final reduction ----------------
__global__ void reduce_kernel(float* __restrict__ out) {
    __shared__ float sh[256];
    int tid = threadIdx.x;
    float s = 0.f;
    for (int i = tid; i < TSTEPS * NBATCH; i += 256) s += g_nll[i];
    sh[tid] = s;
    __syncthreads();
    for (int o = 128; o > 0; o >>= 1) {
        if (tid < o) sh[tid] += sh[tid + o];
        __syncthreads();
    }
    if (tid == 0) out[0] = sh[0] * (1.f / NBATCH);
}

// ---------------- launch ----------------
extern "C" void kernel_launch(void* const* d_in, const int* in_sizes, int n_in,
                              void* d_out, int out_size) {
    const int*   captions = (const int*)d_in[0];
    const float* W_embed  = (const float*)d_in[1];
    const float* Wx       = (const float*)d_in[2];
    const float* Wh       = (const float*)d_in[3];
    const float* b        = (const float*)d_in[4];
    const float* W_vocab  = (const float*)d_in[5];
    const float* b_vocab  = (const float*)d_in[6];
    const float* h_init   = (const float*)d_in[7];

    init_kernel<<<32, 256>>>(h_init);
    embed_xw_kernel<<<TSTEPS * 8, 256>>>(captions, W_embed, Wx, b);
    lstm_kernel<<<128, 256>>>(Wh);
    vocab_kernel<<<TSTEPS, 256>>>(W_vocab, b_vocab, captions);
    reduce_kernel<<<1, 256>>>((float*)d_out);
}

// round 2
// speedup vs baseline: 1.0016x; 1.0016x over previous
#include <cuda_runtime.h>
#include <math.h>

#define VOCABSZ 32000
#define WORDVEC 256
#define HIDDEN  512
#define TSTEPS  256
#define NBATCH  16
#define G4      2048   // 4*HIDDEN

// ---------------- scratch (static device globals; no allocation) ----------------
__device__ float    g_xw[TSTEPS * NBATCH * G4];       // [t][n][4H]  33.5 MB
__device__ float    g_hall[TSTEPS * NBATCH * HIDDEN]; // [t][n][H]    8.4 MB
__device__ float    g_h[NBATCH * HIDDEN];
__device__ float    g_c[NBATCH * HIDDEN];
__device__ float    g_part[4 * NBATCH * G4];          // k-chunk partials
__device__ unsigned g_barc[1024];                     // barrier counters
__device__ float    g_nll[TSTEPS * NBATCH];

// ---------------- helpers ----------------
__device__ __forceinline__ float sigf(float x) {
    return __fdividef(1.f, 1.f + __expf(-x));
}
__device__ __forceinline__ float tanhf_fast(float x) {
    return __fdividef(2.f, 1.f + __expf(-2.f * x)) - 1.f;
}

// software grid barrier: each barrier index used exactly once per launch
__device__ __forceinline__ void grid_barrier(int idx, unsigned nblocks) {
    __threadfence();
    __syncthreads();
    if (threadIdx.x == 0) {
        atomicAdd(&g_barc[idx], 1u);
        volatile unsigned* p = &g_barc[idx];
        while (*p < nblocks) { }
        __threadfence();
    }
    __syncthreads();
}

// ---------------- init: reset mutable state every launch ----------------
__global__ void init_kernel(const float* __restrict__ h_init) {
    int i = blockIdx.x * blockDim.x + threadIdx.x;
    if (i < 1024) g_barc[i] = 0u;
    if (i < NBATCH * HIDDEN) {
        g_h[i] = h_init[i & (HIDDEN - 1)];
        g_c[i] = 0.f;
    }
}

// ---------------- embed gather + xw = x@Wx + b ----------------
// grid: 256 t * 8 k-tiles; block 256 threads. Each thread: one k column, 16 batch rows.
__global__ void __launch_bounds__(256) embed_xw_kernel(
    const int* __restrict__ captions, const float* __restrict__ W_embed,
    const float* __restrict__ Wx, const float* __restrict__ b)
{
    const int t   = blockIdx.x >> 3;
    const int kt  = blockIdx.x & 7;
    const int tid = threadIdx.x;

    __shared__ __align__(16) float x_sh[WORDVEC * 20]; // [d][n] stride 20 (pad)
    __shared__ int tok[NBATCH];
    if (tid < NBATCH) tok[tid] = captions[tid * 257 + t];  // cap_in[n][t]
    __syncthreads();

    #pragma unroll
    for (int i = 0; i < 16; ++i) {           // n = i, d = tid
        x_sh[tid * 20 + i] = W_embed[tok[i] * WORDVEC + tid];
    }
    __syncthreads();

    const int k = kt * 256 + tid;
    float acc[16];
    const float bk = b[k];
    #pragma unroll
    for (int n = 0; n < 16; ++n) acc[n] = bk;

    #pragma unroll 4
    for (int d = 0; d < WORDVEC; ++d) {
        float w = Wx[d * G4 + k];
        float4 h0 = *(const float4*)&x_sh[d * 20 + 0];
        float4 h1 = *(const float4*)&x_sh[d * 20 + 4];
        float4 h2 = *(const float4*)&x_sh[d * 20 + 8];
        float4 h3 = *(const float4*)&x_sh[d * 20 + 12];
        acc[0]  = fmaf(h0.x, w, acc[0]);  acc[1]  = fmaf(h0.y, w, acc[1]);
        acc[2]  = fmaf(h0.z, w, acc[2]);  acc[3]  = fmaf(h0.w, w, acc[3]);
        acc[4]  = fmaf(h1.x, w, acc[4]);  acc[5]  = fmaf(h1.y, w, acc[5]);
        acc[6]  = fmaf(h1.z, w, acc[6]);  acc[7]  = fmaf(h1.w, w, acc[7]);
        acc[8]  = fmaf(h2.x, w, acc[8]);  acc[9]  = fmaf(h2.y, w, acc[9]);
        acc[10] = fmaf(h2.z, w, acc[10]); acc[11] = fmaf(h2.w, w, acc[11]);
        acc[12] = fmaf(h3.x, w, acc[12]); acc[13] = fmaf(h3.y, w, acc[13]);
        acc[14] = fmaf(h3.z, w, acc[14]); acc[15] = fmaf(h3.w, w, acc[15]);
    }
    float* o = &g_xw[(t * NBATCH) * G4 + k];
    #pragma unroll
    for (int n = 0; n < 16; ++n) o[n * G4] = acc[n];
}

// ---------------- persistent LSTM scan ----------------
// 128 blocks x 256 threads; block = (jt 0..31 [64 j-cols], kc 0..3 [128 k]).
// Phase1: partial a = h @ Wh over k-chunk -> g_part. barrier.
// Phase2: first 8192 threads: gates + c/h update. barrier.
__global__ void __launch_bounds__(256) lstm_kernel(const float* __restrict__ Wh) {
    const int bid = blockIdx.x, tid = threadIdx.x;
    const int jt = bid & 31, kc = bid >> 5;
    const int jq = tid & 15, nn = tid >> 4;
    const int jcol = jt * 16 + jq;               // float4 column 0..511
    __shared__ __align__(16) float h_sh[NBATCH * 128];
    const float4* __restrict__ Wh4 = (const float4*)Wh;

    int bi = 0;
    for (int t = 0; t < TSTEPS; ++t) {
        // load this block's k-slice of h (written by other blocks last step -> .cg)
        #pragma unroll
        for (int i = 0; i < 8; ++i) {
            int idx = tid + i * 256;             // n*128 + k
            int n = idx >> 7, k = idx & 127;
            h_sh[idx] = __ldcg(&g_h[n * HIDDEN + kc * 128 + k]);
        }
        __syncthreads();

        float4 a = make_float4(0.f, 0.f, 0.f, 0.f);
        const float* hp = &h_sh[nn * 128];
        #pragma unroll 4
        for (int k = 0; k < 128; ++k) {
            float hv = hp[k];
            float4 w = Wh4[(kc * 128 + k) * 512 + jcol];
            a.x = fmaf(hv, w.x, a.x);
            a.y = fmaf(hv, w.y, a.y);
            a.z = fmaf(hv, w.z, a.z);
            a.w = fmaf(hv, w.w, a.w);
        }
        float* gp = &g_part[(kc * NBATCH + nn) * G4 + jcol * 4];
        gp[0] = a.x; gp[1] = a.y; gp[2] = a.z; gp[3] = a.w;

        grid_barrier(bi++, 128);

        int gidx = bid * 256 + tid;
        if (gidx < NBATCH * HIDDEN) {
            int n = gidx >> 9, h = gidx & 511;
            float av[4];
            #pragma unroll
            for (int g = 0; g < 4; ++g) {
                int col = g * HIDDEN + h;
                float s = g_xw[(t * NBATCH + n) * G4 + col];
                #pragma unroll
                for (int q = 0; q < 4; ++q)
                    s += __ldcg(&g_part[(q * NBATCH + n) * G4 + col]);
                av[g] = s;
            }
            float ig = sigf(av[0]);
            float fg = sigf(av[1]);
            float og = sigf(av[2]);
            float gg = tanhf_fast(av[3]);
            float c  = fg * g_c[gidx] + ig * gg;
            float hh = og * tanhf_fast(c);
            g_c[gidx] = c;
            g_h[gidx] = hh;
            g_hall[t * (NBATCH * HIDDEN) + gidx] = hh;
        }
        grid_barrier(bi++, 128);
    }
}

// ---------------- vocab projection + streaming log-softmax NLL ----------------
// 256 blocks (one per t) x 256 threads; 16-row register blocking; online LSE.
__global__ void __launch_bounds__(256) vocab_kernel(
    const float* __restrict__ Wv, const float* __restrict__ bv,
    const int* __restrict__ captions)
{
    const int t = blockIdx.x, tid = threadIdx.x;
    __shared__ __align__(16) float h_sh[HIDDEN * 20];  // [k][n] stride 20
    __shared__ float red_m[8][16], red_s[8][16];
    __shared__ float sh_lt[16];
    __shared__ int   sh_tg[16];

    if (tid < 16) sh_tg[tid] = captions[tid * 257 + t + 1];  // cap_out[n][t]
    #pragma unroll
    for (int i = 0; i < 32; ++i) {
        int idx = tid + i * 256;                 // n*512 + k
        int n = idx >> 9, k = idx & 511;
        h_sh[k * 20 + n] = g_hall[t * (NBATCH * HIDDEN) + idx];
    }
    __syncthreads();

    float m[16], s[16];
    int tg[16];
    #pragma unroll
    for (int n = 0; n < 16; ++n) { m[n] = -3.0e38f; s[n] = 0.f; tg[n] = sh_tg[n]; }

    for (int vi = 0; vi < VOCABSZ / 256; ++vi) {
        int v = tid + vi * 256;
        float acc[16];
        float bvv = bv[v];
        #pragma unroll
        for (int n = 0; n < 16; ++n) acc[n] = bvv;

        #pragma unroll 4
        for (int k = 0; k < HIDDEN; ++k) {
            float w = Wv[k * VOCABSZ + v];
            float4 h0 = *(const float4*)&h_sh[k * 20 + 0];
            float4 h1 = *(const float4*)&h_sh[k * 20 + 4];
            float4 h2 = *(const float4*)&h_sh[k * 20 + 8];
            float4 h3 = *(const float4*)&h_sh[k * 20 + 12];
            acc[0]  = fmaf(h0.x, w, acc[0]);  acc[1]  = fmaf(h0.y, w, acc[1]);
            acc[2]  = fmaf(h0.z, w, acc[2]);  acc[3]  = fmaf(h0.w, w, acc[3]);
            acc[4]  = fmaf(h1.x, w, acc[4]);  acc[5]  = fmaf(h1.y, w, acc[5]);
            acc[6]  = fmaf(h1.z, w, acc[6]);  acc[7]  = fmaf(h1.w, w, acc[7]);
            acc[8]  = fmaf(h2.x, w, acc[8]);  acc[9]  = fmaf(h2.y, w, acc[9]);
            acc[10] = fmaf(h2.z, w, acc[10]); acc[11] = fmaf(h2.w, w, acc[11]);
            acc[12] = fmaf(h3.x, w, acc[12]); acc[13] = fmaf(h3.w == h3.w ? h3.w : 0.f, 0.f, acc[13]); // placeholder fixed below
            acc[13] = fmaf(h3.y, w, acc[13]);
            acc[14] = fmaf(h3.z, w, acc[14]); acc[15] = fmaf(h3.w, w, acc[15]);
        }
        #pragma unroll
        for (int n = 0; n < 16; ++n) {
            float l = acc[n];
            if (v == tg[n]) sh_lt[n] = l;
            float nm = fmaxf(m[n], l);
            s[n] = s[n] * __expf(m[n] - nm) + __expf(l - nm);
            m[n] = nm;
        }
    }

    // warp-level (m,s) reduction per row
    #pragma unroll
    for (int off = 16; off > 0; off >>= 1) {
        #pragma unroll
        for (int n = 0; n < 16; ++n) {
            float mo = __shfl_down_sync(0xffffffffu, m[n], off);
            float so = __shfl_down_sync(0xffffffffu, s[n], off);
            float nm = fmaxf(m[n], mo);
            s[n] = s[n] * __expf(m[n] - nm) + so * __expf(mo - nm);
            m[n] = nm;
        }
    }
    int wid = tid >> 5, lane = tid & 31;
    if (lane == 0) {
        #pragma unroll
        for (int n = 0; n < 16; ++n) { red_m[wid][n] = m[n]; red_s[wid][n] = s[n]; }
    }
    __syncthreads();

    if (tid < 16) {
        int n = tid;
        float M = red_m[0][n], S = red_s[0][n];
        #pragma unroll
        for (int w = 1; w < 8; ++w) {
            float mo = red_m[w][n], so = red_s[w][n];
            float nm = fmaxf(M, mo);
            S = S * __expf(M - nm) + so * __expf(mo - nm);
            M = nm;
        }
        float lse = M + logf(S);
        float nll = (sh_tg[n] != 0) ? (lse - sh_lt[n]) : 0.f;
        g_nll[t * 16 + n] = nll;
    }
}

// ---------------- deterministic final reduction ----------------
__global__ void reduce_kernel(float* __restrict__ out) {
    __shared__ float sh[256];
    int tid = threadIdx.x;
    float s = 0.f;
    for (int i = tid; i < TSTEPS * NBATCH; i += 256) s += g_nll[i];
    sh[tid] = s;
    __syncthreads();
    for (int o = 128; o > 0; o >>= 1) {
        if (tid < o) sh[tid] += sh[tid + o];
        __syncthreads();
    }
    if (tid == 0) out[0] = sh[0] * (1.f / NBATCH);
}

// ---------------- launch ----------------
extern "C" void kernel_launch(void* const* d_in, const int* in_sizes, int n_in,
                              void* d_out, int out_size) {
    const int*   captions = (const int*)d_in[0];
    const float* W_embed  = (const float*)d_in[1];
    const float* Wx       = (const float*)d_in[2];
    const float* Wh       = (const float*)d_in[3];
    const float* b        = (const float*)d_in[4];
    const float* W_vocab  = (const float*)d_in[5];
    const float* b_vocab  = (const float*)d_in[6];
    const float* h_init   = (const float*)d_in[7];

    init_kernel<<<32, 256>>>(h_init);
    embed_xw_kernel<<<TSTEPS * 8, 256>>>(captions, W_embed, Wx, b);
    lstm_kernel<<<128, 256>>>(Wh);
    vocab_kernel<<<TSTEPS, 256>>>(W_vocab, b_vocab, captions);
    reduce_kernel<<<1, 256>>>((float*)d_out);
}

// round 5
// speedup vs baseline: 7.0833x; 7.0719x over previous
#include <cuda_runtime.h>
#include <cuda_bf16.h>
#include <cstdint>
#include <math.h>

#define VOCABSZ 32000
#define VPAD    32128
#define WORDVEC 256
#define HIDDEN  512
#define TSTEPS  256
#define NBATCH  16
#define G4      2048
#define MROWS   4096
#define NGRP    4
#define GCOLS   8000          // cols per group
#define VTILES  63            // 62 full 128-tiles + tail (62*128+64 = 8000)
#define LOG2E   1.44269504f

// ---------------- device scratch ----------------
__device__ float          g_xw[TSTEPS * NBATCH * G4];
__device__ float          g_hall[MROWS * HIDDEN];          // [t][n][k] fp32
__device__ __nv_bfloat16  g_hb[MROWS * HIDDEN];            // bf16 copy
__device__ __nv_bfloat16  g_wvb[(size_t)VPAD * HIDDEN];    // Wv^T bf16 [v][k], padded
__device__ float          g_bv2[VPAD];                     // bv * LOG2E (pad=0)
__device__ float          g_hT2[2][HIDDEN * NBATCH];       // h state double buffer [k][n]
__device__ unsigned       g_barc[256];
__device__ float          g_ps[NGRP * MROWS];              // partial exp-sums
__device__ float          g_lt[MROWS];                     // target logits (fp32)

// ---------------- helpers ----------------
__device__ __forceinline__ float sigf(float x) { return __fdividef(1.f, 1.f + __expf(-x)); }
__device__ __forceinline__ float tanhf_fast(float x) { return __fdividef(2.f, 1.f + __expf(-2.f * x)) - 1.f; }
__device__ __forceinline__ uint32_t smem_to_u32(const void* p) {
    uint32_t a;
    asm("{ .reg .u64 t; cvta.to.shared.u64 t, %1; cvt.u32.u64 %0, t; }" : "=r"(a) : "l"(p));
    return a;
}
#define LDSM_X4(r, addr) asm volatile( \
    "ldmatrix.sync.aligned.m8n8.x4.shared.b16 {%0,%1,%2,%3}, [%4];" \
    : "=r"((r)[0]), "=r"((r)[1]), "=r"((r)[2]), "=r"((r)[3]) : "r"(addr))
#define MMA16816(d, a, b0, b1) asm volatile( \
    "mma.sync.aligned.m16n8k16.row.col.f32.bf16.bf16.f32 " \
    "{%0,%1,%2,%3}, {%4,%5,%6,%7}, {%8,%9}, {%0,%1,%2,%3};" \
    : "+f"((d)[0]), "+f"((d)[1]), "+f"((d)[2]), "+f"((d)[3]) \
    : "r"((a)[0]), "r"((a)[1]), "r"((a)[2]), "r"((a)[3]), "r"(b0), "r"(b1))

// exp(t*ln2) = 2^t via round-to-nearest split + deg-5 Taylor on [-0.5,0.5]
__device__ __forceinline__ float exp2_fast(float t) {
    int i = __float2int_rn(t);
    float f = t - (float)i;
    float p = fmaf(f, 0.00133335581f, 0.00961812911f);
    p = fmaf(f, p, 0.0555041087f);
    p = fmaf(f, p, 0.240226507f);
    p = fmaf(f, p, 0.693147181f);
    p = fmaf(f, p, 1.0f);
    return __int_as_float(__float_as_int(p) + (i << 23));
}

__device__ __forceinline__ void grid_barrier(int idx, unsigned nblocks) {
    __threadfence();
    __syncthreads();
    if (threadIdx.x == 0) {
        atomicAdd(&g_barc[idx], 1u);
        volatile unsigned* p = &g_barc[idx];
        while (*p < nblocks) { }
        __threadfence();
    }
    __syncthreads();
}

// ---------------- init (every launch) ----------------
__global__ void __launch_bounds__(256) init_kernel(
    const float* __restrict__ h_init, const float* __restrict__ bv)
{
    int gid = blockIdx.x * 256 + threadIdx.x;            // 8192 threads
    if (gid < 256) g_barc[gid] = 0u;
    if (gid < HIDDEN * NBATCH) g_hT2[0][gid] = h_init[gid >> 4];
    // zero pad rows of g_wvb
    for (int j = gid; j < (VPAD - VOCABSZ) * HIDDEN; j += 8192)
        g_wvb[(size_t)VOCABSZ * HIDDEN + j] = __float2bfloat16(0.f);
    for (int j = gid; j < VPAD; j += 8192)
        g_bv2[j] = (j < VOCABSZ) ? bv[j] * LOG2E : 0.f;
}

// ---------------- Wv transpose + bf16: [512,32000] -> [32000,512] ----------------
__global__ void __launch_bounds__(256) conv_wv_kernel(const float* __restrict__ Wv) {
    __shared__ float sh[32 * 33];
    int n0 = blockIdx.x * 32, k0 = blockIdx.y * 32;
    int tx = threadIdx.x & 31, ty = threadIdx.x >> 5;
    #pragma unroll
    for (int i = 0; i < 4; ++i) {
        int k = ty + i * 8;
        sh[k * 33 + tx] = Wv[(size_t)(k0 + k) * VOCABSZ + n0 + tx];
    }
    __syncthreads();
    #pragma unroll
    for (int i = 0; i < 4; ++i) {
        int n = ty + i * 8;
        g_wvb[(size_t)(n0 + n) * HIDDEN + k0 + tx] = __float2bfloat16(sh[tx * 33 + n]);
    }
}

// ---------------- hall -> bf16 ----------------
__global__ void conv_h_kernel() {
    int i = blockIdx.x * blockDim.x + threadIdx.x;
    if (i < MROWS * HIDDEN) g_hb[i] = __float2bfloat16(g_hall[i]);
}

// ---------------- embed gather + xw = x@Wx + b ----------------
__global__ void __launch_bounds__(256) embed_xw_kernel(
    const int* __restrict__ captions, const float* __restrict__ W_embed,
    const float* __restrict__ Wx, const float* __restrict__ b)
{
    const int t = blockIdx.x >> 3, kt = blockIdx.x & 7, tid = threadIdx.x;
    __shared__ __align__(16) float x_sh[WORDVEC * 20];
    __shared__ int tok[NBATCH];
    if (tid < NBATCH) tok[tid] = captions[tid * 257 + t];
    __syncthreads();
    #pragma unroll
    for (int i = 0; i < 16; ++i) x_sh[tid * 20 + i] = W_embed[tok[i] * WORDVEC + tid];
    __syncthreads();

    const int k = kt * 256 + tid;
    float acc[16];
    const float bk = b[k];
    #pragma unroll
    for (int n = 0; n < 16; ++n) acc[n] = bk;
    #pragma unroll 4
    for (int d = 0; d < WORDVEC; ++d) {
        float w = Wx[d * G4 + k];
        float4 h0 = *(const float4*)&x_sh[d * 20 + 0];
        float4 h1 = *(const float4*)&x_sh[d * 20 + 4];
        float4 h2 = *(const float4*)&x_sh[d * 20 + 8];
        float4 h3 = *(const float4*)&x_sh[d * 20 + 12];
        acc[0]=fmaf(h0.x,w,acc[0]);  acc[1]=fmaf(h0.y,w,acc[1]);  acc[2]=fmaf(h0.z,w,acc[2]);  acc[3]=fmaf(h0.w,w,acc[3]);
        acc[4]=fmaf(h1.x,w,acc[4]);  acc[5]=fmaf(h1.y,w,acc[5]);  acc[6]=fmaf(h1.z,w,acc[6]);  acc[7]=fmaf(h1.w,w,acc[7]);
        acc[8]=fmaf(h2.x,w,acc[8]);  acc[9]=fmaf(h2.y,w,acc[9]);  acc[10]=fmaf(h2.z,w,acc[10]); acc[11]=fmaf(h2.w,w,acc[11]);
        acc[12]=fmaf(h3.x,w,acc[12]); acc[13]=fmaf(h3.y,w,acc[13]); acc[14]=fmaf(h3.z,w,acc[14]); acc[15]=fmaf(h3.w,w,acc[15]);
    }
    float* o = &g_xw[(t * NBATCH) * G4 + k];
    #pragma unroll
    for (int n = 0; n < 16; ++n) o[n * G4] = acc[n];
}

// ---------------- persistent LSTM: 128 blocks, double-buffered h, 1 barrier/step --------
extern __shared__ float dsm_l[];
__global__ void __launch_bounds__(256) lstm_kernel(const float* __restrict__ Wh) {
    float* Whs  = dsm_l;           // [512][16]
    float* h_sh = dsm_l + 8192;    // [512][16]
    float* part = dsm_l + 16384;   // [256][16]
    float* a_sh = dsm_l + 20480;   // [256]
    float* c_sh = dsm_l + 20736;   // [64]

    const int bid = blockIdx.x, tid = threadIdx.x;
    const int h0 = bid * 4;
    const int kc = tid >> 4, j16 = tid & 15;

    for (int i = tid; i < 8192; i += 256) {
        int k = i >> 4, j = i & 15;
        int jcol = (j >> 2) * 512 + h0 + (j & 3);
        Whs[i] = Wh[k * G4 + jcol];
    }
    if (tid < 64) c_sh[tid] = 0.f;

    const int gn = tid >> 2, ghq = tid & 3;
    const int ghcol = h0 + ghq;

    for (int t = 0; t < TSTEPS; ++t) {
        float4* h4 = (float4*)h_sh;
        const float4* src4 = (const float4*)g_hT2[t & 1];
        #pragma unroll
        for (int i = 0; i < 8; ++i) h4[tid + i * 256] = __ldcg(&src4[tid + i * 256]);

        float xwv[4];
        if (tid < 64) {
            #pragma unroll
            for (int g = 0; g < 4; ++g)
                xwv[g] = g_xw[(t * NBATCH + gn) * G4 + g * 512 + ghcol];
        }
        __syncthreads();

        float acc[16];
        #pragma unroll
        for (int n = 0; n < 16; ++n) acc[n] = 0.f;
        const float4* hp = (const float4*)h_sh + kc * 128;
        #pragma unroll 2
        for (int kk = 0; kk < 32; ++kk) {
            float w = Whs[(kc * 32 + kk) * 16 + j16];
            float4 a0 = hp[kk * 4 + 0], a1 = hp[kk * 4 + 1], a2 = hp[kk * 4 + 2], a3 = hp[kk * 4 + 3];
            acc[0]=fmaf(a0.x,w,acc[0]);  acc[1]=fmaf(a0.y,w,acc[1]);  acc[2]=fmaf(a0.z,w,acc[2]);  acc[3]=fmaf(a0.w,w,acc[3]);
            acc[4]=fmaf(a1.x,w,acc[4]);  acc[5]=fmaf(a1.y,w,acc[5]);  acc[6]=fmaf(a1.z,w,acc[6]);  acc[7]=fmaf(a1.w,w,acc[7]);
            acc[8]=fmaf(a2.x,w,acc[8]);  acc[9]=fmaf(a2.y,w,acc[9]);  acc[10]=fmaf(a2.z,w,acc[10]); acc[11]=fmaf(a2.w,w,acc[11]);
            acc[12]=fmaf(a3.x,w,acc[12]); acc[13]=fmaf(a3.y,w,acc[13]); acc[14]=fmaf(a3.z,w,acc[14]); acc[15]=fmaf(a3.w,w,acc[15]);
        }
        float4* pp = (float4*)(part + tid * 16);
        pp[0] = make_float4(acc[0], acc[1], acc[2], acc[3]);
        pp[1] = make_float4(acc[4], acc[5], acc[6], acc[7]);
        pp[2] = make_float4(acc[8], acc[9], acc[10], acc[11]);
        pp[3] = make_float4(acc[12], acc[13], acc[14], acc[15]);
        __syncthreads();

        float ssum = 0.f;
        #pragma unroll
        for (int q = 0; q < 16; ++q) ssum += part[q * 256 + tid];
        a_sh[tid] = ssum;
        __syncthreads();

        if (tid < 64) {
            float av0 = a_sh[(0 * 4 + ghq) * 16 + gn] + xwv[0];
            float av1 = a_sh[(1 * 4 + ghq) * 16 + gn] + xwv[1];
            float av2 = a_sh[(2 * 4 + ghq) * 16 + gn] + xwv[2];
            float av3 = a_sh[(3 * 4 + ghq) * 16 + gn] + xwv[3];
            float ig = sigf(av0), fg = sigf(av1), og = sigf(av2), gg = tanhf_fast(av3);
            float c  = fg * c_sh[tid] + ig * gg;
            float hh = og * tanhf_fast(c);
            c_sh[tid] = c;
            g_hT2[(t & 1) ^ 1][ghcol * 16 + gn] = hh;
            g_hall[t * (NBATCH * HIDDEN) + gn * HIDDEN + ghcol] = hh;
        }
        grid_barrier(t, 128);
    }
}

// ---------------- target logits: g_lt[r] = dot(h[r], Wv[:,tg]) + bv[tg] ----------------
__global__ void __launch_bounds__(256) tgt_kernel(
    const int* __restrict__ captions, const float* __restrict__ bv)
{
    int wid = threadIdx.x >> 5, lane = threadIdx.x & 31;
    int r = blockIdx.x * 8 + wid;                        // 512 blocks x 8 warps = 4096
    int tg = captions[(r & 15) * 257 + (r >> 4) + 1];
    const float* hr = &g_hall[r * HIDDEN];
    const __nv_bfloat16* wv = &g_wvb[(size_t)tg * HIDDEN];
    float s = 0.f;
    #pragma unroll
    for (int i = 0; i < 16; ++i) {
        int k = lane + i * 32;
        s = fmaf(hr[k], __bfloat162float(wv[k]), s);
    }
    #pragma unroll
    for (int o = 16; o > 0; o >>= 1) s += __shfl_xor_sync(0xffffffffu, s, o);
    if (lane == 0) g_lt[r] = s + bv[tg];
}

// ---------------- vocab: mma.sync bf16 GEMM + streaming exp-sum ----------------
// grid 128 = 32 mblk x 4 groups; 256 threads (8 warps, warp tile 32m x 64n).
// SMEM: A [128][520] bf16 (133120B) | B 2x[128][72] bf16 (36864B) | red [128][2] f32
#define V_A_STRIDE 520
#define V_B_OFF    133120
#define V_B_SZ     18432
#define V_B_STRIDE 72
#define V_RED_OFF  169984
#define V_SMEM     171008
extern __shared__ __align__(16) char dsm_v[];
__global__ void __launch_bounds__(256, 1) vocab_kernel() {
    __nv_bfloat16* As = (__nv_bfloat16*)dsm_v;
    const int tid = threadIdx.x, lane = tid & 31, wid = tid >> 5;
    const int wm = wid >> 1, wn = wid & 1;
    const int mblk = blockIdx.x >> 2, g = blockIdx.x & 3;
    const int gbase = g * GCOLS;

    // load A tile (128 rows x 512 k) into padded smem
    {
        const uint4* src = (const uint4*)(g_hb + (size_t)(mblk * 128) * HIDDEN);
        for (int i = tid; i < 8192; i += 256) {
            int r = i >> 6, u = i & 63;
            *(uint4*)(As + r * V_A_STRIDE + u * 8) = src[i];
        }
    }
    __syncthreads();

    const uint32_t a_base = smem_to_u32(dsm_v);
    // per-lane A ldmatrix sub-address
    const uint32_t a_lane = (uint32_t)((lane & 15) * V_A_STRIDE + (lane >> 4) * 8) * 2;
    // per-lane B ldmatrix sub-address: quad = lane>>3
    const int bq = lane >> 3;
    const uint32_t b_lane = (uint32_t)(((bq >> 1) * 8 + (lane & 7)) * V_B_STRIDE + (bq & 1) * 8) * 2;

    float rs[2][2] = {{0.f, 0.f}, {0.f, 0.f}};   // running exp-sums per (mt, rh)

    for (int tt = 0; tt < VTILES; ++tt) {
        const int nbase = gbase + tt * 128;
        // bias (pre-scaled) for this thread's 16 columns
        float bb[16];
        {
            int cb = nbase + wn * 64 + (lane & 3) * 2;
            #pragma unroll
            for (int nt = 0; nt < 8; ++nt) {
                bb[nt * 2 + 0] = g_bv2[cb + nt * 8 + 0];
                bb[nt * 2 + 1] = g_bv2[cb + nt * 8 + 1];
            }
        }
        float d[2][8][4];
        #pragma unroll
        for (int mt = 0; mt < 2; ++mt)
            #pragma unroll
            for (int nt = 0; nt < 8; ++nt)
                #pragma unroll
                for (int e = 0; e < 4; ++e) d[mt][nt][e] = 0.f;

        // ---- chunk 0 stage ----
        uint4 ld[4];
        #pragma unroll
        for (int q = 0; q < 4; ++q) {
            int j = q * 256 + tid;
            int n = j >> 3, u = j & 7;
            ld[q] = *(const uint4*)(g_wvb + (size_t)(nbase + n) * HIDDEN + u * 8);
        }
        #pragma unroll
        for (int q = 0; q < 4; ++q) {
            int j = q * 256 + tid;
            int n = j >> 3, u = j & 7;
            *(uint4*)((__nv_bfloat16*)(dsm_v + V_B_OFF) + n * V_B_STRIDE + u * 8) = ld[q];
        }
        __syncthreads();

        for (int kc = 0; kc < 8; ++kc) {
            if (kc < 7) {
                #pragma unroll
                for (int q = 0; q < 4; ++q) {
                    int j = q * 256 + tid;
                    int n = j >> 3, u = j & 7;
                    ld[q] = *(const uint4*)(g_wvb + (size_t)(nbase + n) * HIDDEN + (kc + 1) * 64 + u * 8);
                }
            }
            // ---- mma on buf[kc&1] ----
            const uint32_t b_base = smem_to_u32(dsm_v + V_B_OFF + (kc & 1) * V_B_SZ) + (uint32_t)(wn * 64 * V_B_STRIDE) * 2;
            #pragma unroll
            for (int k16 = 0; k16 < 4; ++k16) {
                uint32_t a[2][4];
                #pragma unroll
                for (int mt = 0; mt < 2; ++mt) {
                    uint32_t aaddr = a_base + a_lane +
                        (uint32_t)((wm * 32 + mt * 16) * V_A_STRIDE + kc * 64 + k16 * 16) * 2;
                    LDSM_X4(a[mt], aaddr);
                }
                #pragma unroll
                for (int np = 0; np < 4; ++np) {
                    uint32_t b[4];
                    uint32_t baddr = b_base + b_lane + (uint32_t)(np * 16 * V_B_STRIDE + k16 * 16) * 2;
                    LDSM_X4(b, baddr);
                    MMA16816(d[0][np * 2 + 0], a[0], b[0], b[1]);
                    MMA16816(d[0][np * 2 + 1], a[0], b[2], b[3]);
                    MMA16816(d[1][np * 2 + 0], a[1], b[0], b[1]);
                    MMA16816(d[1][np * 2 + 1], a[1], b[2], b[3]);
                }
            }
            if (kc < 7) {
                __nv_bfloat16* dst = (__nv_bfloat16*)(dsm_v + V_B_OFF + ((kc + 1) & 1) * V_B_SZ);
                #pragma unroll
                for (int q = 0; q < 4; ++q) {
                    int j = q * 256 + tid;
                    int n = j >> 3, u = j & 7;
                    *(uint4*)(dst + n * V_B_STRIDE + u * 8) = ld[q];
                }
            }
            __syncthreads();
        }

        // ---- epilogue: exp-sum (tail tile: only wn==0, cols 0..63 valid) ----
        if (!(tt == VTILES - 1 && wn == 1)) {
            #pragma unroll
            for (int mt = 0; mt < 2; ++mt)
                #pragma unroll
                for (int rh = 0; rh < 2; ++rh) {
                    float s = 0.f;
                    #pragma unroll
                    for (int nt = 0; nt < 8; ++nt) {
                        s += exp2_fast(fmaf(d[mt][nt][rh * 2 + 0], LOG2E, bb[nt * 2 + 0]));
                        s += exp2_fast(fmaf(d[mt][nt][rh * 2 + 1], LOG2E, bb[nt * 2 + 1]));
                    }
                    rs[mt][rh] += s;
                }
        }
    }

    // reduce: lanes sharing a row are lane^1, lane^2
    float* red = (float*)(dsm_v + V_RED_OFF);
    #pragma unroll
    for (int mt = 0; mt < 2; ++mt)
        #pragma unroll
        for (int rh = 0; rh < 2; ++rh) {
            float v = rs[mt][rh];
            v += __shfl_xor_sync(0xffffffffu, v, 1);
            v += __shfl_xor_sync(0xffffffffu, v, 2);
            if ((lane & 3) == 0) {
                int row = wm * 32 + mt * 16 + rh * 8 + (lane >> 2);
                red[row * 2 + wn] = v;
            }
        }
    __syncthreads();
    if (tid < 128) {
        g_ps[g * MROWS + mblk * 128 + tid] = red[tid * 2 + 0] + red[tid * 2 + 1];
    }
}

// ---------------- combine: loss = sum mask*(log(sum_g S_g) - lt) / N ----------------
__global__ void __launch_bounds__(1024) combine_kernel(
    const int* __restrict__ captions, float* __restrict__ out)
{
    __shared__ float sh[1024];
    int tid = threadIdx.x;
    float local = 0.f;
    for (int r = tid; r < MROWS; r += 1024) {
        float S = g_ps[r] + g_ps[MROWS + r] + g_ps[2 * MROWS + r] + g_ps[3 * MROWS + r];
        int tg = captions[(r & 15) * 257 + (r >> 4) + 1];
        if (tg != 0) local += logf(S) - g_lt[r];
    }
    sh[tid] = local;
    __syncthreads();
    for (int o = 512; o > 0; o >>= 1) {
        if (tid < o) sh[tid] += sh[tid + o];
        __syncthreads();
    }
    if (tid == 0) out[0] = sh[0] * (1.f / NBATCH);
}

// ---------------- launch ----------------
extern "C" void kernel_launch(void* const* d_in, const int* in_sizes, int n_in,
                              void* d_out, int out_size) {
    const int*   captions = (const int*)d_in[0];
    const float* W_embed  = (const float*)d_in[1];
    const float* Wx       = (const float*)d_in[2];
    const float* Wh       = (const float*)d_in[3];
    const float* b        = (const float*)d_in[4];
    const float* W_vocab  = (const float*)d_in[5];
    const float* b_vocab  = (const float*)d_in[6];
    const float* h_init   = (const float*)d_in[7];

    cudaFuncSetAttribute(lstm_kernel,  cudaFuncAttributeMaxDynamicSharedMemorySize, 83200);
    cudaFuncSetAttribute(vocab_kernel, cudaFuncAttributeMaxDynamicSharedMemorySize, V_SMEM);

    init_kernel<<<32, 256>>>(h_init, b_vocab);
    conv_wv_kernel<<<dim3(VOCABSZ / 32, HIDDEN / 32), 256>>>(W_vocab);
    embed_xw_kernel<<<TSTEPS * 8, 256>>>(captions, W_embed, Wx, b);
    lstm_kernel<<<128, 256, 83200>>>(Wh);
    conv_h_kernel<<<(MROWS * HIDDEN) / 256, 256>>>();
    tgt_kernel<<<512, 256>>>(captions, b_vocab);
    vocab_kernel<<<128, 256, V_SMEM>>>();
    combine_kernel<<<1, 1024>>>(captions, (float*)d_out);
}

// round 6
// speedup vs baseline: 7.6249x; 1.0765x over previous
#include <cuda_runtime.h>
#include <cuda_bf16.h>
#include <cstdint>
#include <math.h>

#define VOCABSZ 32000
#define VPAD    32128
#define WORDVEC 256
#define HIDDEN  512
#define TSTEPS  256
#define NBATCH  16
#define G4      2048
#define MROWS   4096
#define NGRP    4
#define GCOLS   8000
#define VTILES  63
#define LOG2E   1.44269504f

// ---------------- device scratch ----------------
__device__ float          g_xw[TSTEPS * NBATCH * G4];
__device__ float          g_hall[MROWS * HIDDEN];          // [t][n][k] fp32
__device__ __nv_bfloat16  g_hb[MROWS * HIDDEN];            // bf16 copy (written by lstm)
__device__ __nv_bfloat16  g_wvb[(size_t)VPAD * HIDDEN];    // Wv^T bf16 [v][k]
__device__ __nv_bfloat16  g_xb[MROWS * WORDVEC];           // gathered embeddings bf16
__device__ __nv_bfloat16  g_wxT[G4 * WORDVEC];             // Wx^T bf16 [j][d]
__device__ float          g_bv2[VPAD];                     // bv * LOG2E
__device__ float          g_hT2[2][HIDDEN * NBATCH];       // h state double buffer [k][n]
__device__ unsigned       g_barc[256];
__device__ float          g_ps[NGRP * MROWS];
__device__ float          g_lt[MROWS];

// ---------------- helpers ----------------
__device__ __forceinline__ float sigf(float x) { return __fdividef(1.f, 1.f + __expf(-x)); }
__device__ __forceinline__ float tanhf_fast(float x) { return __fdividef(2.f, 1.f + __expf(-2.f * x)) - 1.f; }
__device__ __forceinline__ uint32_t smem_to_u32(const void* p) {
    uint32_t a;
    asm("{ .reg .u64 t; cvta.to.shared.u64 t, %1; cvt.u32.u64 %0, t; }" : "=r"(a) : "l"(p));
    return a;
}
#define LDSM_X4(r, addr) asm volatile( \
    "ldmatrix.sync.aligned.m8n8.x4.shared.b16 {%0,%1,%2,%3}, [%4];" \
    : "=r"((r)[0]), "=r"((r)[1]), "=r"((r)[2]), "=r"((r)[3]) : "r"(addr))
#define MMA16816(d, a, b0, b1) asm volatile( \
    "mma.sync.aligned.m16n8k16.row.col.f32.bf16.bf16.f32 " \
    "{%0,%1,%2,%3}, {%4,%5,%6,%7}, {%8,%9}, {%0,%1,%2,%3};" \
    : "+f"((d)[0]), "+f"((d)[1]), "+f"((d)[2]), "+f"((d)[3]) \
    : "r"((a)[0]), "r"((a)[1]), "r"((a)[2]), "r"((a)[3]), "r"(b0), "r"(b1))

__device__ __forceinline__ float exp2_fast(float t) {
    int i = __float2int_rn(t);
    float f = t - (float)i;
    float p = fmaf(f, 0.00133335581f, 0.00961812911f);
    p = fmaf(f, p, 0.0555041087f);
    p = fmaf(f, p, 0.240226507f);
    p = fmaf(f, p, 0.693147181f);
    p = fmaf(f, p, 1.0f);
    return __int_as_float(__float_as_int(p) + (i << 23));
}

__device__ __forceinline__ void grid_barrier(int idx, unsigned nblocks) {
    __threadfence();
    __syncthreads();
    if (threadIdx.x == 0) {
        atomicAdd(&g_barc[idx], 1u);
        volatile unsigned* p = &g_barc[idx];
        while (*p < nblocks) { }
        __threadfence();
    }
    __syncthreads();
}

// ---------------- init ----------------
__global__ void __launch_bounds__(256) init_kernel(
    const float* __restrict__ h_init, const float* __restrict__ bv)
{
    int gid = blockIdx.x * 256 + threadIdx.x;            // 8192 threads
    if (gid < 256) g_barc[gid] = 0u;
    if (gid < HIDDEN * NBATCH) g_hT2[0][gid] = h_init[gid >> 4];
    for (int j = gid; j < (VPAD - VOCABSZ) * HIDDEN; j += 8192)
        g_wvb[(size_t)VOCABSZ * HIDDEN + j] = __float2bfloat16(0.f);
    for (int j = gid; j < VPAD; j += 8192)
        g_bv2[j] = (j < VOCABSZ) ? bv[j] * LOG2E : 0.f;
}

// ---------------- Wv transpose + bf16 ----------------
__global__ void __launch_bounds__(256) conv_wv_kernel(const float* __restrict__ Wv) {
    __shared__ float sh[32 * 33];
    int n0 = blockIdx.x * 32, k0 = blockIdx.y * 32;
    int tx = threadIdx.x & 31, ty = threadIdx.x >> 5;
    #pragma unroll
    for (int i = 0; i < 4; ++i) {
        int k = ty + i * 8;
        sh[k * 33 + tx] = Wv[(size_t)(k0 + k) * VOCABSZ + n0 + tx];
    }
    __syncthreads();
    #pragma unroll
    for (int i = 0; i < 4; ++i) {
        int n = ty + i * 8;
        g_wvb[(size_t)(n0 + n) * HIDDEN + k0 + tx] = __float2bfloat16(sh[tx * 33 + n]);
    }
}

// ---------------- Wx transpose + bf16: [256][2048] -> [2048][256] ----------------
__global__ void __launch_bounds__(256) conv_wx_kernel(const float* __restrict__ Wx) {
    __shared__ float sh[32 * 33];
    int n0 = blockIdx.x * 32, k0 = blockIdx.y * 32;
    int tx = threadIdx.x & 31, ty = threadIdx.x >> 5;
    #pragma unroll
    for (int i = 0; i < 4; ++i) {
        int k = ty + i * 8;
        sh[k * 33 + tx] = Wx[(k0 + k) * G4 + n0 + tx];
    }
    __syncthreads();
    #pragma unroll
    for (int i = 0; i < 4; ++i) {
        int n = ty + i * 8;
        g_wxT[(n0 + n) * WORDVEC + k0 + tx] = __float2bfloat16(sh[tx * 33 + n]);
    }
}

// ---------------- gather embeddings -> bf16 A [4096][256] ----------------
__global__ void __launch_bounds__(256) gather_x_kernel(
    const int* __restrict__ captions, const float* __restrict__ W_embed)
{
    int gid = blockIdx.x * 256 + threadIdx.x;     // 65536 threads, 4 elems each
    int idx = gid * 4;
    int r = idx >> 8, d = idx & 255;
    int tok = captions[(r & 15) * 257 + (r >> 4)];   // cap_in[n][t], r = t*16+n
    float4 v = *(const float4*)&W_embed[tok * WORDVEC + d];
    __nv_bfloat16 o[4];
    o[0] = __float2bfloat16(v.x); o[1] = __float2bfloat16(v.y);
    o[2] = __float2bfloat16(v.z); o[3] = __float2bfloat16(v.w);
    *(uint2*)&g_xb[idx] = *(const uint2*)o;
}

// ---------------- embed GEMM: xw = x@Wx + b via mma.sync ----------------
// grid 512 = 32 mblk x 16 nblk; 256 threads (8 warps, warp tile 32m x 64n). K=256 resident.
#define E_A_STRIDE 264
#define E_B_OFF    67584
#define E_SMEM     135168
extern __shared__ __align__(16) char dsm_e[];
__global__ void __launch_bounds__(256, 1) embed_mma_kernel(const float* __restrict__ b) {
    __nv_bfloat16* As = (__nv_bfloat16*)dsm_e;
    __nv_bfloat16* Bs = (__nv_bfloat16*)(dsm_e + E_B_OFF);
    const int tid = threadIdx.x, lane = tid & 31, wid = tid >> 5;
    const int wm = wid >> 1, wn = wid & 1;
    const int mblk = blockIdx.x >> 4, nblk = blockIdx.x & 15;

    const uint4* asrc = (const uint4*)(g_xb + mblk * 128 * WORDVEC);
    const uint4* bsrc = (const uint4*)(g_wxT + nblk * 128 * WORDVEC);
    #pragma unroll
    for (int q = 0; q < 16; ++q) {
        int i = q * 256 + tid;                 // 4096 uint4 (= 128 rows x 32)
        int r = i >> 5, u = i & 31;
        *(uint4*)(As + r * E_A_STRIDE + u * 8) = asrc[i];
        *(uint4*)(Bs + r * E_A_STRIDE + u * 8) = bsrc[i];
    }
    __syncthreads();

    const uint32_t a_base = smem_to_u32(As);
    const uint32_t a_lane = (uint32_t)((lane & 15) * E_A_STRIDE + (lane >> 4) * 8) * 2;
    const int bq = lane >> 3;
    const uint32_t b_lane = (uint32_t)(((bq >> 1) * 8 + (lane & 7)) * E_A_STRIDE + (bq & 1) * 8) * 2;
    const uint32_t b_base = smem_to_u32(Bs) + (uint32_t)(wn * 64 * E_A_STRIDE) * 2;

    float d[2][8][4];
    #pragma unroll
    for (int mt = 0; mt < 2; ++mt)
        #pragma unroll
        for (int nt = 0; nt < 8; ++nt)
            #pragma unroll
            for (int e = 0; e < 4; ++e) d[mt][nt][e] = 0.f;

    #pragma unroll
    for (int k16 = 0; k16 < 16; ++k16) {
        const uint32_t koff = (uint32_t)(k16 * 16) * 2;
        uint32_t a[2][4];
        #pragma unroll
        for (int mt = 0; mt < 2; ++mt) {
            LDSM_X4(a[mt], a_base + a_lane + (uint32_t)((wm * 32 + mt * 16) * E_A_STRIDE) * 2 + koff);
        }
        #pragma unroll
        for (int np = 0; np < 4; ++np) {
            uint32_t bb[4];
            LDSM_X4(bb, b_base + b_lane + (uint32_t)(np * 16 * E_A_STRIDE) * 2 + koff);
            MMA16816(d[0][np * 2 + 0], a[0], bb[0], bb[1]);
            MMA16816(d[0][np * 2 + 1], a[0], bb[2], bb[3]);
            MMA16816(d[1][np * 2 + 0], a[1], bb[0], bb[1]);
            MMA16816(d[1][np * 2 + 1], a[1], bb[2], bb[3]);
        }
    }

    // epilogue: add bias, store fp32
    const int cbase = nblk * 128 + wn * 64 + (lane & 3) * 2;
    #pragma unroll
    for (int mt = 0; mt < 2; ++mt)
        #pragma unroll
        for (int rh = 0; rh < 2; ++rh) {
            int row = mblk * 128 + wm * 32 + mt * 16 + rh * 8 + (lane >> 2);
            #pragma unroll
            for (int nt = 0; nt < 8; ++nt) {
                int c = cbase + nt * 8;
                float2 v;
                v.x = d[mt][nt][rh * 2 + 0] + b[c];
                v.y = d[mt][nt][rh * 2 + 1] + b[c + 1];
                *(float2*)&g_xw[(size_t)row * G4 + c] = v;
            }
        }
}

// ---------------- persistent LSTM: 128 blocks, double-buffered h, 1 barrier/step --------
extern __shared__ float dsm_l[];
__global__ void __launch_bounds__(256) lstm_kernel(const float* __restrict__ Wh) {
    float* Whs  = dsm_l;           // [512][16]
    float* h_sh = dsm_l + 8192;    // [512][16]
    float* part = dsm_l + 16384;   // [256][16]
    float* a_sh = dsm_l + 20480;   // [256]
    float* c_sh = dsm_l + 20736;   // [64]

    const int bid = blockIdx.x, tid = threadIdx.x;
    const int h0 = bid * 4;
    const int kc = tid >> 4, j16 = tid & 15;

    for (int i = tid; i < 8192; i += 256) {
        int k = i >> 4, j = i & 15;
        int jcol = (j >> 2) * 512 + h0 + (j & 3);
        Whs[i] = Wh[k * G4 + jcol];
    }
    if (tid < 64) c_sh[tid] = 0.f;

    const int gn = tid >> 2, ghq = tid & 3;
    const int ghcol = h0 + ghq;

    for (int t = 0; t < TSTEPS; ++t) {
        float4* h4 = (float4*)h_sh;
        const float4* src4 = (const float4*)g_hT2[t & 1];
        #pragma unroll
        for (int i = 0; i < 8; ++i) h4[tid + i * 256] = __ldcg(&src4[tid + i * 256]);

        float xwv[4];
        if (tid < 64) {
            #pragma unroll
            for (int g = 0; g < 4; ++g)
                xwv[g] = g_xw[(size_t)(t * NBATCH + gn) * G4 + g * 512 + ghcol];
        }
        __syncthreads();

        float acc[16];
        #pragma unroll
        for (int n = 0; n < 16; ++n) acc[n] = 0.f;
        const float4* hp = (const float4*)h_sh + kc * 128;
        #pragma unroll 2
        for (int kk = 0; kk < 32; ++kk) {
            float w = Whs[(kc * 32 + kk) * 16 + j16];
            float4 a0 = hp[kk * 4 + 0], a1 = hp[kk * 4 + 1], a2 = hp[kk * 4 + 2], a3 = hp[kk * 4 + 3];
            acc[0]=fmaf(a0.x,w,acc[0]);  acc[1]=fmaf(a0.y,w,acc[1]);  acc[2]=fmaf(a0.z,w,acc[2]);  acc[3]=fmaf(a0.w,w,acc[3]);
            acc[4]=fmaf(a1.x,w,acc[4]);  acc[5]=fmaf(a1.y,w,acc[5]);  acc[6]=fmaf(a1.z,w,acc[6]);  acc[7]=fmaf(a1.w,w,acc[7]);
            acc[8]=fmaf(a2.x,w,acc[8]);  acc[9]=fmaf(a2.y,w,acc[9]);  acc[10]=fmaf(a2.z,w,acc[10]); acc[11]=fmaf(a2.w,w,acc[11]);
            acc[12]=fmaf(a3.x,w,acc[12]); acc[13]=fmaf(a3.y,w,acc[13]); acc[14]=fmaf(a3.z,w,acc[14]); acc[15]=fmaf(a3.w,w,acc[15]);
        }
        float4* pp = (float4*)(part + tid * 16);
        pp[0] = make_float4(acc[0], acc[1], acc[2], acc[3]);
        pp[1] = make_float4(acc[4], acc[5], acc[6], acc[7]);
        pp[2] = make_float4(acc[8], acc[9], acc[10], acc[11]);
        pp[3] = make_float4(acc[12], acc[13], acc[14], acc[15]);
        __syncthreads();

        float ssum = 0.f;
        #pragma unroll
        for (int q = 0; q < 16; ++q) ssum += part[q * 256 + tid];
        a_sh[tid] = ssum;
        __syncthreads();

        if (tid < 64) {
            float av0 = a_sh[(0 * 4 + ghq) * 16 + gn] + xwv[0];
            float av1 = a_sh[(1 * 4 + ghq) * 16 + gn] + xwv[1];
            float av2 = a_sh[(2 * 4 + ghq) * 16 + gn] + xwv[2];
            float av3 = a_sh[(3 * 4 + ghq) * 16 + gn] + xwv[3];
            float ig = sigf(av0), fg = sigf(av1), og = sigf(av2), gg = tanhf_fast(av3);
            float c  = fg * c_sh[tid] + ig * gg;
            float hh = og * tanhf_fast(c);
            c_sh[tid] = c;
            g_hT2[(t & 1) ^ 1][ghcol * 16 + gn] = hh;
            g_hall[t * (NBATCH * HIDDEN) + gn * HIDDEN + ghcol] = hh;
            g_hb[t * (NBATCH * HIDDEN) + gn * HIDDEN + ghcol] = __float2bfloat16(hh);
        }
        grid_barrier(t, 128);
    }
}

// ---------------- target logits ----------------
__global__ void __launch_bounds__(256) tgt_kernel(
    const int* __restrict__ captions, const float* __restrict__ bv)
{
    int wid = threadIdx.x >> 5, lane = threadIdx.x & 31;
    int r = blockIdx.x * 8 + wid;
    int tg = captions[(r & 15) * 257 + (r >> 4) + 1];
    const float* hr = &g_hall[r * HIDDEN];
    const __nv_bfloat16* wv = &g_wvb[(size_t)tg * HIDDEN];
    float s = 0.f;
    #pragma unroll
    for (int i = 0; i < 16; ++i) {
        int k = lane + i * 32;
        s = fmaf(hr[k], __bfloat162float(wv[k]), s);
    }
    #pragma unroll
    for (int o = 16; o > 0; o >>= 1) s += __shfl_xor_sync(0xffffffffu, s, o);
    if (lane == 0) g_lt[r] = s + bv[tg];
}

// ---------------- vocab: mma.sync bf16 GEMM + streaming exp-sum ----------------
#define V_A_STRIDE 520
#define V_B_OFF    133120
#define V_B_SZ     18432
#define V_B_STRIDE 72
#define V_RED_OFF  169984
#define V_SMEM     171008
extern __shared__ __align__(16) char dsm_v[];
__global__ void __launch_bounds__(256, 1) vocab_kernel() {
    __nv_bfloat16* As = (__nv_bfloat16*)dsm_v;
    const int tid = threadIdx.x, lane = tid & 31, wid = tid >> 5;
    const int wm = wid >> 1, wn = wid & 1;
    const int mblk = blockIdx.x >> 2, g = blockIdx.x & 3;
    const int gbase = g * GCOLS;

    {
        const uint4* src = (const uint4*)(g_hb + (size_t)(mblk * 128) * HIDDEN);
        for (int i = tid; i < 8192; i += 256) {
            int r = i >> 6, u = i & 63;
            *(uint4*)(As + r * V_A_STRIDE + u * 8) = src[i];
        }
    }
    __syncthreads();

    const uint32_t a_base = smem_to_u32(dsm_v);
    const uint32_t a_lane = (uint32_t)((lane & 15) * V_A_STRIDE + (lane >> 4) * 8) * 2;
    const int bq = lane >> 3;
    const uint32_t b_lane = (uint32_t)(((bq >> 1) * 8 + (lane & 7)) * V_B_STRIDE + (bq & 1) * 8) * 2;

    float rs[2][2] = {{0.f, 0.f}, {0.f, 0.f}};

    for (int tt = 0; tt < VTILES; ++tt) {
        const int nbase = gbase + tt * 128;
        float bb[16];
        {
            int cb = nbase + wn * 64 + (lane & 3) * 2;
            #pragma unroll
            for (int nt = 0; nt < 8; ++nt) {
                bb[nt * 2 + 0] = g_bv2[cb + nt * 8 + 0];
                bb[nt * 2 + 1] = g_bv2[cb + nt * 8 + 1];
            }
        }
        float d[2][8][4];
        #pragma unroll
        for (int mt = 0; mt < 2; ++mt)
            #pragma unroll
            for (int nt = 0; nt < 8; ++nt)
                #pragma unroll
                for (int e = 0; e < 4; ++e) d[mt][nt][e] = 0.f;

        uint4 ld[4];
        #pragma unroll
        for (int q = 0; q < 4; ++q) {
            int j = q * 256 + tid;
            int n = j >> 3, u = j & 7;
            ld[q] = *(const uint4*)(g_wvb + (size_t)(nbase + n) * HIDDEN + u * 8);
        }
        #pragma unroll
        for (int q = 0; q < 4; ++q) {
            int j = q * 256 + tid;
            int n = j >> 3, u = j & 7;
            *(uint4*)((__nv_bfloat16*)(dsm_v + V_B_OFF) + n * V_B_STRIDE + u * 8) = ld[q];
        }
        __syncthreads();

        for (int kc = 0; kc < 8; ++kc) {
            if (kc < 7) {
                #pragma unroll
                for (int q = 0; q < 4; ++q) {
                    int j = q * 256 + tid;
                    int n = j >> 3, u = j & 7;
                    ld[q] = *(const uint4*)(g_wvb + (size_t)(nbase + n) * HIDDEN + (kc + 1) * 64 + u * 8);
                }
            }
            const uint32_t b_base = smem_to_u32(dsm_v + V_B_OFF + (kc & 1) * V_B_SZ) + (uint32_t)(wn * 64 * V_B_STRIDE) * 2;
            #pragma unroll
            for (int k16 = 0; k16 < 4; ++k16) {
                uint32_t a[2][4];
                #pragma unroll
                for (int mt = 0; mt < 2; ++mt) {
                    uint32_t aaddr = a_base + a_lane +
                        (uint32_t)((wm * 32 + mt * 16) * V_A_STRIDE + kc * 64 + k16 * 16) * 2;
                    LDSM_X4(a[mt], aaddr);
                }
                #pragma unroll
                for (int np = 0; np < 4; ++np) {
                    uint32_t b[4];
                    uint32_t baddr = b_base + b_lane + (uint32_t)(np * 16 * V_B_STRIDE + k16 * 16) * 2;
                    LDSM_X4(b, baddr);
                    MMA16816(d[0][np * 2 + 0], a[0], b[0], b[1]);
                    MMA16816(d[0][np * 2 + 1], a[0], b[2], b[3]);
                    MMA16816(d[1][np * 2 + 0], a[1], b[0], b[1]);
                    MMA16816(d[1][np * 2 + 1], a[1], b[2], b[3]);
                }
            }
            if (kc < 7) {
                __nv_bfloat16* dst = (__nv_bfloat16*)(dsm_v + V_B_OFF + ((kc + 1) & 1) * V_B_SZ);
                #pragma unroll
                for (int q = 0; q < 4; ++q) {
                    int j = q * 256 + tid;
                    int n = j >> 3, u = j & 7;
                    *(uint4*)(dst + n * V_B_STRIDE + u * 8) = ld[q];
                }
            }
            __syncthreads();
        }

        if (!(tt == VTILES - 1 && wn == 1)) {
            #pragma unroll
            for (int mt = 0; mt < 2; ++mt)
                #pragma unroll
                for (int rh = 0; rh < 2; ++rh) {
                    float s = 0.f;
                    #pragma unroll
                    for (int nt = 0; nt < 8; ++nt) {
                        s += exp2_fast(fmaf(d[mt][nt][rh * 2 + 0], LOG2E, bb[nt * 2 + 0]));
                        s += exp2_fast(fmaf(d[mt][nt][rh * 2 + 1], LOG2E, bb[nt * 2 + 1]));
                    }
                    rs[mt][rh] += s;
                }
        }
    }

    float* red = (float*)(dsm_v + V_RED_OFF);
    #pragma unroll
    for (int mt = 0; mt < 2; ++mt)
        #pragma unroll
        for (int rh = 0; rh < 2; ++rh) {
            float v = rs[mt][rh];
            v += __shfl_xor_sync(0xffffffffu, v, 1);
            v += __shfl_xor_sync(0xffffffffu, v, 2);
            if ((lane & 3) == 0) {
                int row = wm * 32 + mt * 16 + rh * 8 + (lane >> 2);
                red[row * 2 + wn] = v;
            }
        }
    __syncthreads();
    if (tid < 128) {
        g_ps[g * MROWS + mblk * 128 + tid] = red[tid * 2 + 0] + red[tid * 2 + 1];
    }
}

// ---------------- combine ----------------
__global__ void __launch_bounds__(1024) combine_kernel(
    const int* __restrict__ captions, float* __restrict__ out)
{
    __shared__ float sh[1024];
    int tid = threadIdx.x;
    float local = 0.f;
    for (int r = tid; r < MROWS; r += 1024) {
        float S = g_ps[r] + g_ps[MROWS + r] + g_ps[2 * MROWS + r] + g_ps[3 * MROWS + r];
        int tg = captions[(r & 15) * 257 + (r >> 4) + 1];
        if (tg != 0) local += logf(S) - g_lt[r];
    }
    sh[tid] = local;
    __syncthreads();
    for (int o = 512; o > 0; o >>= 1) {
        if (tid < o) sh[tid] += sh[tid + o];
        __syncthreads();
    }
    if (tid == 0) out[0] = sh[0] * (1.f / NBATCH);
}

// ---------------- launch ----------------
extern "C" void kernel_launch(void* const* d_in, const int* in_sizes, int n_in,
                              void* d_out, int out_size) {
    const int*   captions = (const int*)d_in[0];
    const float* W_embed  = (const float*)d_in[1];
    const float* Wx       = (const float*)d_in[2];
    const float* Wh       = (const float*)d_in[3];
    const float* b        = (const float*)d_in[4];
    const float* W_vocab  = (const float*)d_in[5];
    const float* b_vocab  = (const float*)d_in[6];
    const float* h_init   = (const float*)d_in[7];

    cudaFuncSetAttribute(lstm_kernel,      cudaFuncAttributeMaxDynamicSharedMemorySize, 83200);
    cudaFuncSetAttribute(vocab_kernel,     cudaFuncAttributeMaxDynamicSharedMemorySize, V_SMEM);
    cudaFuncSetAttribute(embed_mma_kernel, cudaFuncAttributeMaxDynamicSharedMemorySize, E_SMEM);

    init_kernel<<<32, 256>>>(h_init, b_vocab);
    gather_x_kernel<<<256, 256>>>(captions, W_embed);
    conv_wx_kernel<<<dim3(G4 / 32, WORDVEC / 32), 256>>>(Wx);
    conv_wv_kernel<<<dim3(VOCABSZ / 32, HIDDEN / 32), 256>>>(W_vocab);
    embed_mma_kernel<<<512, 256, E_SMEM>>>(b);
    lstm_kernel<<<128, 256, 83200>>>(Wh);
    tgt_kernel<<<512, 256>>>(captions, b_vocab);
    vocab_kernel<<<128, 256, V_SMEM>>>();
    combine_kernel<<<1, 1024>>>(captions, (float*)d_out);
}